// round 2
// baseline (speedup 1.0000x reference)
#include <cuda_runtime.h>
#include <cuda_bf16.h>

// Problem constants (fixed by the dataset)
#define BB 2
#define NN 16384
#define CC 64
#define SS 4096         // npoint
#define KK 32           // nsample
#define R2 0.16f        // radius^2

// Output layout (float32, flattened tuple):
//   [0, 24576)                      new_xyz  [B,S,3]
//   [24576, 24576+1048576)          new_features [B,128,S]
//   [1073152, 1081344)              samp_idx [B,S] (as float)
#define OUT_XYZ 0
#define OUT_FEAT (BB*SS*3)
#define OUT_IDX  (BB*SS*3 + BB*128*SS)

// Scratch: neighbor indices
__device__ int g_idx[BB * SS * KK];

// ---------------------------------------------------------------------------
// Kernel 1: ball query (+ write new_xyz and samp_idx outputs)
// One thread = one centroid. Block = 64 threads, all same batch.
// xyz tiled through shared memory as float4 (x,y,z,|p|^2); inner-loop reads
// are warp-broadcast LDS.128. Early exit when all centroids in block are full.
// ---------------------------------------------------------------------------
#define BQ_BLK 64
#define BQ_TILE 1024

__global__ void __launch_bounds__(BQ_BLK)
ball_query_kernel(const float* __restrict__ xyz, float* __restrict__ out)
{
    __shared__ float4 tile[BQ_TILE];

    const int tid = threadIdx.x;
    const int b   = blockIdx.x / (SS / BQ_BLK);
    const int s   = (blockIdx.x % (SS / BQ_BLK)) * BQ_BLK + tid;

    const float* xb = xyz + b * NN * 3;

    const float cx = xb[s * 3 + 0];
    const float cy = xb[s * 3 + 1];
    const float cz = xb[s * 3 + 2];
    const float cc = cx * cx + cy * cy + cz * cz;

    // outputs: new_xyz copy + samp_idx
    float* oxyz = out + OUT_XYZ + (b * SS + s) * 3;
    oxyz[0] = cx; oxyz[1] = cy; oxyz[2] = cz;
    out[OUT_IDX + b * SS + s] = (float)s;

    const int base = (b * SS + s) * KK;
    int cnt = 0;

    for (int t0 = 0; t0 < NN; t0 += BQ_TILE) {
        // cooperative tile load
        #pragma unroll
        for (int j = tid; j < BQ_TILE; j += BQ_BLK) {
            const float px = xb[(t0 + j) * 3 + 0];
            const float py = xb[(t0 + j) * 3 + 1];
            const float pz = xb[(t0 + j) * 3 + 2];
            tile[j] = make_float4(px, py, pz, px * px + py * py + pz * pz);
        }
        __syncthreads();

        if (cnt < KK) {
            for (int j = 0; j < BQ_TILE; ++j) {
                const float4 p = tile[j];
                float dot = cx * p.x;
                dot = fmaf(cy, p.y, dot);
                dot = fmaf(cz, p.z, dot);
                const float d2 = fmaf(-2.0f, dot, cc + p.w);
                if (d2 < R2) {
                    g_idx[base + cnt] = t0 + j;
                    ++cnt;
                    if (cnt == KK) break;
                }
            }
        }
        if (__syncthreads_and(cnt >= KK)) break;
    }

    // pad empty slots with first hit (or 0 if no hit)
    const int first = (cnt > 0) ? g_idx[base] : 0;
    for (int k = cnt; k < KK; ++k) g_idx[base + k] = first;
}

// ---------------------------------------------------------------------------
// Kernel 2: gather + 3-layer MLP + max-pool
// One warp = one centroid; lane = sample row. Weights in dynamic smem.
// ---------------------------------------------------------------------------
__device__ __forceinline__ void acc_row64(float* __restrict__ h, float g,
                                          const float* __restrict__ w)
{
    const float4* w4 = reinterpret_cast<const float4*>(w);
    #pragma unroll
    for (int d4 = 0; d4 < 16; ++d4) {
        const float4 wv = w4[d4];
        h[d4 * 4 + 0] = fmaf(g, wv.x, h[d4 * 4 + 0]);
        h[d4 * 4 + 1] = fmaf(g, wv.y, h[d4 * 4 + 1]);
        h[d4 * 4 + 2] = fmaf(g, wv.z, h[d4 * 4 + 2]);
        h[d4 * 4 + 3] = fmaf(g, wv.w, h[d4 * 4 + 3]);
    }
}

#define MLP_BLK 256
#define SMEM_FLOATS (4288 + 4096 + 8192 + 64 + 64 + 128)   // 16832 floats = 67328 B

__global__ void __launch_bounds__(MLP_BLK, 1)
mlp_kernel(const float* __restrict__ xyz, const float* __restrict__ features,
           const float* __restrict__ W1, const float* __restrict__ b1,
           const float* __restrict__ W2, const float* __restrict__ b2,
           const float* __restrict__ W3, const float* __restrict__ b3,
           float* __restrict__ out)
{
    extern __shared__ float sm[];
    float* sW1 = sm;              // [67][64]
    float* sW2 = sW1 + 67 * 64;   // [64][64]
    float* sW3 = sW2 + 64 * 64;   // [64][128]
    float* sb1 = sW3 + 64 * 128;  // [64]
    float* sb2 = sb1 + 64;        // [64]
    float* sb3 = sb2 + 64;        // [128]

    const int tid = threadIdx.x;
    for (int i = tid; i < 67 * 64; i += MLP_BLK) sW1[i] = W1[i];
    for (int i = tid; i < 64 * 64; i += MLP_BLK) sW2[i] = W2[i];
    for (int i = tid; i < 64 * 128; i += MLP_BLK) sW3[i] = W3[i];
    if (tid < 64)  sb1[tid] = b1[tid];
    if (tid < 64)  sb2[tid] = b2[tid];
    if (tid < 128) sb3[tid] = b3[tid];
    __syncthreads();

    const int wid  = tid >> 5;
    const int lane = tid & 31;
    const int cen  = blockIdx.x * (MLP_BLK / 32) + wid;   // 0..8191
    const int b = cen >> 12;
    const int s = cen & (SS - 1);

    const int idx = g_idx[cen * KK + lane];

    const float* xb = xyz + b * NN * 3;
    const float cx = xb[s * 3 + 0];
    const float cy = xb[s * 3 + 1];
    const float cz = xb[s * 3 + 2];
    const float px = xb[idx * 3 + 0] - cx;
    const float py = xb[idx * 3 + 1] - cy;
    const float pz = xb[idx * 3 + 2] - cz;

    // ---- layer 1: 67 -> 64 ----
    float h1[64];
    #pragma unroll
    for (int d = 0; d < 64; ++d) h1[d] = sb1[d];

    acc_row64(h1, px, sW1 + 0 * 64);
    acc_row64(h1, py, sW1 + 1 * 64);
    acc_row64(h1, pz, sW1 + 2 * 64);

    const float* f = features + (long)b * CC * NN + idx;
    #pragma unroll 4
    for (int c = 0; c < CC; ++c) {
        const float gc = __ldg(f + (long)c * NN);
        acc_row64(h1, gc, sW1 + (3 + c) * 64);
    }
    #pragma unroll
    for (int d = 0; d < 64; ++d) h1[d] = fmaxf(h1[d], 0.0f);

    // ---- layer 2: 64 -> 64 ----
    float h2[64];
    #pragma unroll
    for (int d = 0; d < 64; ++d) h2[d] = sb2[d];
    #pragma unroll
    for (int c = 0; c < 64; ++c) acc_row64(h2, h1[c], sW2 + c * 64);
    #pragma unroll
    for (int d = 0; d < 64; ++d) h2[d] = fmaxf(h2[d], 0.0f);

    // ---- layer 3: 64 -> 128, split into two 64-wide halves ----
    float* outf_base = out + OUT_FEAT + ((long)b * 128) * SS + s;
    for (int half = 0; half < 2; ++half) {
        float acc[64];
        #pragma unroll
        for (int d = 0; d < 64; ++d) acc[d] = sb3[half * 64 + d];
        #pragma unroll
        for (int c = 0; c < 64; ++c)
            acc_row64(acc, h2[c], sW3 + c * 128 + half * 64);

        float* outf = outf_base + (long)(half * 64) * SS;
        #pragma unroll
        for (int d = 0; d < 64; ++d) {
            float v = fmaxf(acc[d], 0.0f);   // relu, then max over samples
            v = fmaxf(v, __shfl_xor_sync(0xffffffffu, v, 16));
            v = fmaxf(v, __shfl_xor_sync(0xffffffffu, v, 8));
            v = fmaxf(v, __shfl_xor_sync(0xffffffffu, v, 4));
            v = fmaxf(v, __shfl_xor_sync(0xffffffffu, v, 2));
            v = fmaxf(v, __shfl_xor_sync(0xffffffffu, v, 1));
            if (lane == (d & 31)) outf[(long)d * SS] = v;
        }
    }
}

// ---------------------------------------------------------------------------
extern "C" void kernel_launch(void* const* d_in, const int* in_sizes, int n_in,
                              void* d_out, int out_size)
{
    const float* xyz      = (const float*)d_in[0];
    const float* features = (const float*)d_in[1];
    const float* W1 = (const float*)d_in[2];
    const float* b1 = (const float*)d_in[3];
    const float* W2 = (const float*)d_in[4];
    const float* b2 = (const float*)d_in[5];
    const float* W3 = (const float*)d_in[6];
    const float* b3 = (const float*)d_in[7];
    float* out = (float*)d_out;

    const size_t smem_bytes = SMEM_FLOATS * sizeof(float);
    cudaFuncSetAttribute(mlp_kernel, cudaFuncAttributeMaxDynamicSharedMemorySize,
                         (int)smem_bytes);

    ball_query_kernel<<<BB * SS / BQ_BLK, BQ_BLK>>>(xyz, out);
    mlp_kernel<<<BB * SS / (MLP_BLK / 32), MLP_BLK, smem_bytes>>>(
        xyz, features, W1, b1, W2, b2, W3, b3, out);
}

// round 5
// speedup vs baseline: 2.0382x; 2.0382x over previous
#include <cuda_runtime.h>
#include <cuda_bf16.h>

// Problem constants (fixed by the dataset)
#define BB 2
#define NN 16384
#define CC 64
#define SS 4096         // npoint
#define KK 32           // nsample
#define R2 0.16f        // radius^2

// Output layout (float32, flattened tuple):
//   [0, 24576)             new_xyz  [B,S,3]
//   [24576, +1048576)      new_features [B,128,S]
//   [1073152, 1081344)     samp_idx [B,S] (as float)
#define OUT_XYZ 0
#define OUT_FEAT (BB*SS*3)
#define OUT_IDX  (BB*SS*3 + BB*128*SS)

// Scratch
__device__ int   g_idx[BB * SS * KK];
__device__ float g_ft[BB * NN * CC];     // features transposed to [B][N][C]

// ---------------------------------------------------------------------------
// Kernel 0: transpose features [B][C][N] -> [B][N][C]
// ---------------------------------------------------------------------------
__global__ void __launch_bounds__(256)
transpose_kernel(const float* __restrict__ f)
{
    __shared__ float t[32][33];
    const int b  = blockIdx.z;
    const int n0 = blockIdx.x * 32;
    const int c0 = blockIdx.y * 32;

    for (int i = threadIdx.y; i < 32; i += 8)
        t[i][threadIdx.x] = f[((long)b * CC + c0 + i) * NN + n0 + threadIdx.x];
    __syncthreads();
    for (int i = threadIdx.y; i < 32; i += 8)
        g_ft[((long)b * NN + n0 + i) * CC + c0 + threadIdx.x] = t[threadIdx.x][i];
}

// ---------------------------------------------------------------------------
// Kernel 1: warp-cooperative ball query (+ new_xyz, samp_idx outputs)
// One warp per centroid; lane tests one point per iteration; ballot+prefix
// collects the first KK hits in index order; uniform early exit.
// ---------------------------------------------------------------------------
#define BQ_BLK 256

__global__ void __launch_bounds__(BQ_BLK)
ball_query_kernel(const float* __restrict__ xyz, float* __restrict__ out)
{
    const int cen  = blockIdx.x * (BQ_BLK / 32) + (threadIdx.x >> 5);  // 0..8191
    const int lane = threadIdx.x & 31;
    const int b = cen >> 12;
    const int s = cen & (SS - 1);

    const float* xb = xyz + b * NN * 3;
    const float cx = xb[s * 3 + 0];
    const float cy = xb[s * 3 + 1];
    const float cz = xb[s * 3 + 2];
    const float cc = cx * cx + cy * cy + cz * cz;

    if (lane == 0) {
        float* oxyz = out + OUT_XYZ + (b * SS + s) * 3;
        oxyz[0] = cx; oxyz[1] = cy; oxyz[2] = cz;
        out[OUT_IDX + b * SS + s] = (float)s;
    }

    const int base = cen * KK;
    int cnt = 0;

    for (int t0 = 0; t0 < NN; t0 += 32) {
        const int j = t0 + lane;
        const float px = xb[j * 3 + 0];
        const float py = xb[j * 3 + 1];
        const float pz = xb[j * 3 + 2];
        const float pp = px * px + py * py + pz * pz;
        float dot = cx * px;
        dot = fmaf(cy, py, dot);
        dot = fmaf(cz, pz, dot);
        const float d2 = fmaf(-2.0f, dot, cc + pp);   // same expansion as ref

        const bool hit = d2 < R2;
        const unsigned mask = __ballot_sync(0xffffffffu, hit);
        const int rank = __popc(mask & ((1u << lane) - 1u));
        if (hit && cnt + rank < KK) g_idx[base + cnt + rank] = j;
        cnt += __popc(mask);          // uniform across warp
        if (cnt >= KK) break;         // uniform branch
    }
    if (cnt > KK) cnt = KK;

    __syncwarp();
    int first = 0;
    if (cnt > 0) first = g_idx[base];
    if (lane >= cnt) g_idx[base + lane] = first;
}

// ---------------------------------------------------------------------------
// Kernel 2: gather + 3-layer MLP + max-pool (known-good scalar FFMA path)
// One warp = one centroid; lane = sample row. Weights in dynamic smem.
// ---------------------------------------------------------------------------
__device__ __forceinline__ void acc_row64(float* __restrict__ h, float g,
                                          const float* __restrict__ w)
{
    const float4* w4 = reinterpret_cast<const float4*>(w);
    #pragma unroll
    for (int d4 = 0; d4 < 16; ++d4) {
        const float4 wv = w4[d4];
        h[d4 * 4 + 0] = fmaf(g, wv.x, h[d4 * 4 + 0]);
        h[d4 * 4 + 1] = fmaf(g, wv.y, h[d4 * 4 + 1]);
        h[d4 * 4 + 2] = fmaf(g, wv.z, h[d4 * 4 + 2]);
        h[d4 * 4 + 3] = fmaf(g, wv.w, h[d4 * 4 + 3]);
    }
}

#define MLP_BLK 256
#define SMEM_FLOATS (67*64 + 64*64 + 64*128 + 64 + 64 + 128)   // 16832 floats

__global__ void __launch_bounds__(MLP_BLK, 1)
mlp_kernel(const float* __restrict__ xyz,
           const float* __restrict__ W1, const float* __restrict__ b1,
           const float* __restrict__ W2, const float* __restrict__ b2,
           const float* __restrict__ W3, const float* __restrict__ b3,
           float* __restrict__ out)
{
    extern __shared__ float sm[];
    float* sW1 = sm;              // [67][64]
    float* sW2 = sW1 + 67 * 64;   // [64][64]
    float* sW3 = sW2 + 64 * 64;   // [64][128]
    float* sb1 = sW3 + 64 * 128;  // [64]
    float* sb2 = sb1 + 64;        // [64]
    float* sb3 = sb2 + 64;        // [128]

    const int tid = threadIdx.x;
    for (int i = tid; i < 67 * 64; i += MLP_BLK) sW1[i] = W1[i];
    for (int i = tid; i < 64 * 64; i += MLP_BLK) sW2[i] = W2[i];
    for (int i = tid; i < 64 * 128; i += MLP_BLK) sW3[i] = W3[i];
    if (tid < 64)  sb1[tid] = b1[tid];
    if (tid < 64)  sb2[tid] = b2[tid];
    if (tid < 128) sb3[tid] = b3[tid];
    __syncthreads();

    const int wid  = tid >> 5;
    const int lane = tid & 31;
    const int cen  = blockIdx.x * (MLP_BLK / 32) + wid;   // 0..8191
    const int b = cen >> 12;
    const int s = cen & (SS - 1);

    const int idx = g_idx[cen * KK + lane];

    const float* xb = xyz + b * NN * 3;
    const float cx = xb[s * 3 + 0];
    const float cy = xb[s * 3 + 1];
    const float cz = xb[s * 3 + 2];
    const float px = xb[idx * 3 + 0] - cx;
    const float py = xb[idx * 3 + 1] - cy;
    const float pz = xb[idx * 3 + 2] - cz;

    // ---- layer 1: 67 -> 64 ----
    float h1[64];
    #pragma unroll
    for (int d = 0; d < 64; ++d) h1[d] = sb1[d];

    acc_row64(h1, px, sW1 + 0 * 64);
    acc_row64(h1, py, sW1 + 1 * 64);
    acc_row64(h1, pz, sW1 + 2 * 64);

    // gather this lane's sample features (transposed layout, 16x LDG.128)
    const float4* f4 = reinterpret_cast<const float4*>(g_ft + ((long)b * NN + idx) * CC);
    #pragma unroll 4
    for (int c4 = 0; c4 < 16; ++c4) {
        const float4 g = __ldg(f4 + c4);
        acc_row64(h1, g.x, sW1 + (3 + c4 * 4 + 0) * 64);
        acc_row64(h1, g.y, sW1 + (3 + c4 * 4 + 1) * 64);
        acc_row64(h1, g.z, sW1 + (3 + c4 * 4 + 2) * 64);
        acc_row64(h1, g.w, sW1 + (3 + c4 * 4 + 3) * 64);
    }
    #pragma unroll
    for (int d = 0; d < 64; ++d) h1[d] = fmaxf(h1[d], 0.0f);

    // ---- layer 2: 64 -> 64 ----
    float h2[64];
    #pragma unroll
    for (int d = 0; d < 64; ++d) h2[d] = sb2[d];
    #pragma unroll
    for (int c = 0; c < 64; ++c) acc_row64(h2, h1[c], sW2 + c * 64);
    #pragma unroll
    for (int d = 0; d < 64; ++d) h2[d] = fmaxf(h2[d], 0.0f);

    // ---- layer 3: 64 -> 128, two 64-wide halves ----
    float* outf_base = out + OUT_FEAT + ((long)b * 128) * SS + s;
    #pragma unroll 1
    for (int half = 0; half < 2; ++half) {
        float acc[64];
        #pragma unroll
        for (int d = 0; d < 64; ++d) acc[d] = sb3[half * 64 + d];
        #pragma unroll
        for (int c = 0; c < 64; ++c)
            acc_row64(acc, h2[c], sW3 + c * 128 + half * 64);

        float* outf = outf_base + (long)(half * 64) * SS;
        #pragma unroll
        for (int d = 0; d < 64; ++d) {
            float v = fmaxf(acc[d], 0.0f);   // relu, then max over samples
            v = fmaxf(v, __shfl_xor_sync(0xffffffffu, v, 16));
            v = fmaxf(v, __shfl_xor_sync(0xffffffffu, v, 8));
            v = fmaxf(v, __shfl_xor_sync(0xffffffffu, v, 4));
            v = fmaxf(v, __shfl_xor_sync(0xffffffffu, v, 2));
            v = fmaxf(v, __shfl_xor_sync(0xffffffffu, v, 1));
            if (lane == (d & 31)) outf[(long)d * SS] = v;
        }
    }
}

// ---------------------------------------------------------------------------
extern "C" void kernel_launch(void* const* d_in, const int* in_sizes, int n_in,
                              void* d_out, int out_size)
{
    const float* xyz      = (const float*)d_in[0];
    const float* features = (const float*)d_in[1];
    const float* W1 = (const float*)d_in[2];
    const float* b1 = (const float*)d_in[3];
    const float* W2 = (const float*)d_in[4];
    const float* b2 = (const float*)d_in[5];
    const float* W3 = (const float*)d_in[6];
    const float* b3 = (const float*)d_in[7];
    float* out = (float*)d_out;

    const size_t smem_bytes = SMEM_FLOATS * sizeof(float);
    cudaFuncSetAttribute(mlp_kernel, cudaFuncAttributeMaxDynamicSharedMemorySize,
                         (int)smem_bytes);

    transpose_kernel<<<dim3(NN / 32, CC / 32, BB), dim3(32, 8)>>>(features);
    ball_query_kernel<<<BB * SS / (BQ_BLK / 32), BQ_BLK>>>(xyz, out);
    mlp_kernel<<<BB * SS / (MLP_BLK / 32), MLP_BLK, smem_bytes>>>(
        xyz, W1, b1, W2, b2, W3, b3, out);
}

// round 6
// speedup vs baseline: 2.3362x; 1.1462x over previous
#include <cuda_runtime.h>
#include <cuda_bf16.h>

// Problem constants (fixed by the dataset)
#define BB 2
#define NN 16384
#define CC 64
#define SS 4096         // npoint
#define KK 32           // nsample
#define R2 0.16f        // radius^2

// Output layout (float32, flattened tuple):
//   [0, 24576)             new_xyz  [B,S,3]
//   [24576, +1048576)      new_features [B,128,S]
//   [1073152, 1081344)     samp_idx [B,S] (as float)
#define OUT_XYZ 0
#define OUT_FEAT (BB*SS*3)
#define OUT_IDX  (BB*SS*3 + BB*128*SS)

// Scratch
__device__ int    g_idx[BB * SS * KK];
__device__ float  g_ft[BB * NN * CC];    // features transposed to [B][N][C]
__device__ float4 g_pt[BB * NN];         // (x, y, z, |p|^2)

// ---------------------------------------------------------------------------
// Kernel 0a: build point table (x,y,z,|p|^2)
// ---------------------------------------------------------------------------
__global__ void __launch_bounds__(256)
prep_pt_kernel(const float* __restrict__ xyz)
{
    const int i = blockIdx.x * 256 + threadIdx.x;   // 0 .. BB*NN-1
    const float px = xyz[i * 3 + 0];
    const float py = xyz[i * 3 + 1];
    const float pz = xyz[i * 3 + 2];
    g_pt[i] = make_float4(px, py, pz, px * px + py * py + pz * pz);
}

// ---------------------------------------------------------------------------
// Kernel 0b: transpose features [B][C][N] -> [B][N][C]
// ---------------------------------------------------------------------------
__global__ void __launch_bounds__(256)
transpose_kernel(const float* __restrict__ f)
{
    __shared__ float t[32][33];
    const int b  = blockIdx.z;
    const int n0 = blockIdx.x * 32;
    const int c0 = blockIdx.y * 32;

    for (int i = threadIdx.y; i < 32; i += 8)
        t[i][threadIdx.x] = f[((long)b * CC + c0 + i) * NN + n0 + threadIdx.x];
    __syncthreads();
    for (int i = threadIdx.y; i < 32; i += 8)
        g_ft[((long)b * NN + n0 + i) * CC + c0 + threadIdx.x] = t[threadIdx.x][i];
}

// ---------------------------------------------------------------------------
// Kernel 1: warp-cooperative ball query (+ new_xyz, samp_idx outputs)
// One warp per centroid; lane tests one point/iter via one LDG.128 from g_pt;
// ballot+prefix collects first KK hits in index order; uniform early exit.
// ---------------------------------------------------------------------------
#define BQ_BLK 256

__global__ void __launch_bounds__(BQ_BLK)
ball_query_kernel(float* __restrict__ out)
{
    const int cen  = blockIdx.x * (BQ_BLK / 32) + (threadIdx.x >> 5);  // 0..8191
    const int lane = threadIdx.x & 31;
    const int b = cen >> 12;
    const int s = cen & (SS - 1);

    const float4 c4 = g_pt[b * NN + s];
    const float cx = c4.x, cy = c4.y, cz = c4.z, cc = c4.w;

    if (lane == 0) {
        float* oxyz = out + OUT_XYZ + (b * SS + s) * 3;
        oxyz[0] = cx; oxyz[1] = cy; oxyz[2] = cz;
        out[OUT_IDX + b * SS + s] = (float)s;
    }

    const int base = cen * KK;
    const float4* pt = g_pt + b * NN;
    int cnt = 0;

    for (int t0 = 0; t0 < NN; t0 += 32) {
        const int j = t0 + lane;
        const float4 p = pt[j];
        float dot = cx * p.x;
        dot = fmaf(cy, p.y, dot);
        dot = fmaf(cz, p.z, dot);
        const float d2 = fmaf(-2.0f, dot, cc + p.w);

        const bool hit = d2 < R2;
        const unsigned mask = __ballot_sync(0xffffffffu, hit);
        const int rank = __popc(mask & ((1u << lane) - 1u));
        if (hit && cnt + rank < KK) g_idx[base + cnt + rank] = j;
        cnt += __popc(mask);          // uniform across warp
        if (cnt >= KK) break;         // uniform branch
    }
    if (cnt > KK) cnt = KK;

    __syncwarp();
    int first = 0;
    if (cnt > 0) first = g_idx[base];
    if (lane >= cnt) g_idx[base + lane] = first;
}

// ---------------------------------------------------------------------------
// Kernel 2: gather + 3-layer MLP + max-pool.
// 512 threads = 16 warps = 8 centroids; a warp PAIR shares one centroid.
// Warp parity p owns 32 output channels per layer (32 accumulators/thread
// -> regs <= 128 -> 16 warps/SM). Activations exchanged via smem staging.
// ---------------------------------------------------------------------------
__device__ __forceinline__ void acc_row32(float* __restrict__ h, float g,
                                          const float* __restrict__ w)
{
    const float4* w4 = reinterpret_cast<const float4*>(w);
    #pragma unroll
    for (int i = 0; i < 8; ++i) {
        const float4 wv = w4[i];
        h[i * 4 + 0] = fmaf(g, wv.x, h[i * 4 + 0]);
        h[i * 4 + 1] = fmaf(g, wv.y, h[i * 4 + 1]);
        h[i * 4 + 2] = fmaf(g, wv.z, h[i * 4 + 2]);
        h[i * 4 + 3] = fmaf(g, wv.w, h[i * 4 + 3]);
    }
}

#define MLP_BLK 512
#define CEN_PER_CTA 8
#define W_FLOATS (67*64 + 64*64 + 64*128 + 64 + 64 + 128)       // 16832
#define HB_FLOATS (CEN_PER_CTA * 64 * 32)                        // 16384
#define SMEM_FLOATS (W_FLOATS + HB_FLOATS)                       // 33216 = 132864 B

__global__ void __launch_bounds__(MLP_BLK)
mlp_kernel(const float* __restrict__ W1, const float* __restrict__ b1,
           const float* __restrict__ W2, const float* __restrict__ b2,
           const float* __restrict__ W3, const float* __restrict__ b3,
           float* __restrict__ out)
{
    extern __shared__ float sm[];
    float* sW1 = sm;              // [67][64]
    float* sW2 = sW1 + 67 * 64;   // [64][64]
    float* sW3 = sW2 + 64 * 64;   // [64][128]
    float* sb1 = sW3 + 64 * 128;  // [64]
    float* sb2 = sb1 + 64;        // [64]
    float* sb3 = sb2 + 64;        // [128]
    float* hb  = sb3 + 128;       // [8][64][32] activation staging

    const int tid = threadIdx.x;
    {   // vectorized weight copy
        float4* d1 = (float4*)sW1;  const float4* s1 = (const float4*)W1;
        for (int i = tid; i < 67 * 16; i += MLP_BLK) d1[i] = s1[i];
        float4* d2 = (float4*)sW2;  const float4* s2 = (const float4*)W2;
        for (int i = tid; i < 64 * 16; i += MLP_BLK) d2[i] = s2[i];
        float4* d3 = (float4*)sW3;  const float4* s3 = (const float4*)W3;
        for (int i = tid; i < 64 * 32; i += MLP_BLK) d3[i] = s3[i];
        if (tid < 64)  sb1[tid] = b1[tid];
        if (tid < 64)  sb2[tid] = b2[tid];
        if (tid < 128) sb3[tid] = b3[tid];
    }
    __syncthreads();

    const int wid  = tid >> 5;
    const int lane = tid & 31;
    const int cl   = wid >> 1;          // local centroid 0..7
    const int p    = wid & 1;           // channel-half
    const int cen  = blockIdx.x * CEN_PER_CTA + cl;   // 0..8191
    const int b = cen >> 12;
    const int s = cen & (SS - 1);

    const int idx = g_idx[cen * KK + lane];

    const float4 c4 = g_pt[b * NN + s];
    const float4 p4 = g_pt[b * NN + idx];
    const float px = p4.x - c4.x;
    const float py = p4.y - c4.y;
    const float pz = p4.z - c4.z;

    float* hrow = hb + cl * (64 * 32);   // [64][32] for this centroid

    // ---- layer 1: 67 -> 64 (this warp: channels [32p, 32p+32)) ----
    float acc[32];
    #pragma unroll
    for (int j = 0; j < 32; ++j) acc[j] = sb1[32 * p + j];

    acc_row32(acc, px, sW1 + 0 * 64 + 32 * p);
    acc_row32(acc, py, sW1 + 1 * 64 + 32 * p);
    acc_row32(acc, pz, sW1 + 2 * 64 + 32 * p);

    const float4* f4 = reinterpret_cast<const float4*>(g_ft + ((long)b * NN + idx) * CC);
    #pragma unroll 4
    for (int c4i = 0; c4i < 16; ++c4i) {
        const float4 g = __ldg(f4 + c4i);
        acc_row32(acc, g.x, sW1 + (3 + c4i * 4 + 0) * 64 + 32 * p);
        acc_row32(acc, g.y, sW1 + (3 + c4i * 4 + 1) * 64 + 32 * p);
        acc_row32(acc, g.z, sW1 + (3 + c4i * 4 + 2) * 64 + 32 * p);
        acc_row32(acc, g.w, sW1 + (3 + c4i * 4 + 3) * 64 + 32 * p);
    }
    // relu + stage h1
    #pragma unroll
    for (int j = 0; j < 32; ++j)
        hrow[(32 * p + j) * 32 + lane] = fmaxf(acc[j], 0.0f);
    __syncthreads();

    // ---- layer 2: 64 -> 64 ----
    float acc2[32];
    #pragma unroll
    for (int j = 0; j < 32; ++j) acc2[j] = sb2[32 * p + j];
    #pragma unroll 4
    for (int c = 0; c < 64; ++c) {
        const float g = hrow[c * 32 + lane];
        acc_row32(acc2, g, sW2 + c * 64 + 32 * p);
    }
    __syncthreads();   // everyone done READING h1 before overwriting with h2
    #pragma unroll
    for (int j = 0; j < 32; ++j)
        hrow[(32 * p + j) * 32 + lane] = fmaxf(acc2[j], 0.0f);
    __syncthreads();

    // ---- layer 3: 64 -> 128 (this warp: [64p, 64p+64) in 2 chunks of 32) ----
    float* outf = out + OUT_FEAT + ((long)b * 128) * SS + s;
    #pragma unroll 1
    for (int q = 0; q < 2; ++q) {
        const int ch0 = 64 * p + 32 * q;
        float acc3[32];
        #pragma unroll
        for (int j = 0; j < 32; ++j) acc3[j] = sb3[ch0 + j];
        #pragma unroll 4
        for (int c = 0; c < 64; ++c) {
            const float g = hrow[c * 32 + lane];
            acc_row32(acc3, g, sW3 + c * 128 + ch0);
        }
        #pragma unroll
        for (int j = 0; j < 32; ++j) {
            float v = fmaxf(acc3[j], 0.0f);          // relu, then max over samples
            v = fmaxf(v, __shfl_xor_sync(0xffffffffu, v, 16));
            v = fmaxf(v, __shfl_xor_sync(0xffffffffu, v, 8));
            v = fmaxf(v, __shfl_xor_sync(0xffffffffu, v, 4));
            v = fmaxf(v, __shfl_xor_sync(0xffffffffu, v, 2));
            v = fmaxf(v, __shfl_xor_sync(0xffffffffu, v, 1));
            if (lane == j) outf[(long)(ch0 + j) * SS] = v;
        }
    }
}

// ---------------------------------------------------------------------------
extern "C" void kernel_launch(void* const* d_in, const int* in_sizes, int n_in,
                              void* d_out, int out_size)
{
    const float* xyz      = (const float*)d_in[0];
    const float* features = (const float*)d_in[1];
    const float* W1 = (const float*)d_in[2];
    const float* b1 = (const float*)d_in[3];
    const float* W2 = (const float*)d_in[4];
    const float* b2 = (const float*)d_in[5];
    const float* W3 = (const float*)d_in[6];
    const float* b3 = (const float*)d_in[7];
    float* out = (float*)d_out;

    const size_t smem_bytes = SMEM_FLOATS * sizeof(float);
    cudaFuncSetAttribute(mlp_kernel, cudaFuncAttributeMaxDynamicSharedMemorySize,
                         (int)smem_bytes);

    prep_pt_kernel<<<BB * NN / 256, 256>>>(xyz);
    transpose_kernel<<<dim3(NN / 32, CC / 32, BB), dim3(32, 8)>>>(features);
    ball_query_kernel<<<BB * SS / (BQ_BLK / 32), BQ_BLK>>>(out);
    mlp_kernel<<<BB * SS / CEN_PER_CTA, MLP_BLK, smem_bytes>>>(
        W1, b1, W2, b2, W3, b3, out);
}